// round 15
// baseline (speedup 1.0000x reference)
#include <cuda_runtime.h>
#include <cuda_fp16.h>
#include <cstdint>
#include <math.h>

#define N_ROWS 4096
#define DIMS   128
#define NJ     4
#define TOPK   16

// smem map (bytes): A (32KB) + double-buffered B (2 x 32KB) = 96KB
#define SM_AHI  0
#define SM_B0   32768
#define SM_B1   65536
#define SM_TOTAL 98304

// ---------------- device scratch (static, allocation-free) ----------------
__device__ __half g_fhi[N_ROWS * DIMS];
__device__ __half g_nhi[(size_t)NJ * N_ROWS * DIMS];
__device__ __half g_sims[(size_t)NJ * N_ROWS * N_ROWS];   // 128 MB fp16
__device__ float g_topbuf[N_ROWS * NJ * TOPK];
__device__ float g_part[256];

// ---------------- PTX helpers (base-arch portable: no tcgen05) ----------------
__device__ __forceinline__ uint32_t smem_u32(const void* p) {
    uint32_t a;
    asm("{ .reg .u64 t; cvta.to.shared.u64 t, %1; cvt.u32.u64 %0, t; }" : "=r"(a) : "l"(p));
    return a;
}
__device__ __forceinline__ void ldsm4(uint32_t* r, uint32_t a) {
    asm volatile("ldmatrix.sync.aligned.m8n8.x4.shared.b16 {%0,%1,%2,%3}, [%4];"
                 : "=r"(r[0]), "=r"(r[1]), "=r"(r[2]), "=r"(r[3]) : "r"(a));
}
__device__ __forceinline__ void mma16816(float* c, const uint32_t* a,
                                         uint32_t b0, uint32_t b1) {
    asm("mma.sync.aligned.m16n8k16.row.col.f32.f16.f16.f32 "
        "{%0,%1,%2,%3}, {%4,%5,%6,%7}, {%8,%9}, {%0,%1,%2,%3};"
        : "+f"(c[0]), "+f"(c[1]), "+f"(c[2]), "+f"(c[3])
        : "r"(a[0]), "r"(a[1]), "r"(a[2]), "r"(a[3]), "r"(b0), "r"(b1));
}

// Byte offset of (row, col) in a 128x128 fp16 tile stored as 8-row x 128B
// blocked atoms with SW128 XOR swizzle. col must be a multiple of 8.
__device__ __forceinline__ uint32_t toff(int row, int col) {
    return (uint32_t)(((row >> 3) + (col >> 6) * 16) * 1024 + (row & 7) * 128 +
                      ((((col >> 3) & 7) ^ (row & 7)) * 16));
}

// Stage a 128x128 fp16 tile (row-major in gmem) into swizzled smem via cp.async.
// 512-thread version: 2048 16B chunks, 4 per thread.
__device__ __forceinline__ void stage_async(uint32_t sdst,
                                            const __half* __restrict__ g,
                                            int t) {
#pragma unroll
    for (int i = 0; i < 4; i++) {
        int c = t + 512 * i;              // 0..2047 16B chunks
        int row = c >> 4, kch = c & 15;
        uint32_t dst = sdst + toff(row, kch * 8);
        const void* src = g + row * DIMS + kch * 8;
        asm volatile("cp.async.cg.shared.global [%0], [%1], 16;" :: "r"(dst), "l"(src));
    }
}

// ---------------- kernel 0: normalize + fp16 convert ----------------
__global__ void convert_kernel(const float* __restrict__ feat,
                               const float* __restrict__ negs) {
    int gw = (blockIdx.x * blockDim.x + threadIdx.x) >> 5;
    int lane = threadIdx.x & 31;
    if (gw >= N_ROWS + NJ * N_ROWS) return;
    const float* src;
    __half* dh;
    if (gw < N_ROWS) {
        src = feat + (size_t)gw * DIMS;
        dh = g_fhi + (size_t)gw * DIMS;
    } else {
        int r = gw - N_ROWS;
        src = negs + (size_t)r * DIMS;
        dh = g_nhi + (size_t)r * DIMS;
    }
    float4 v = ((const float4*)src)[lane];
    float s = v.x * v.x + v.y * v.y + v.z * v.z + v.w * v.w;
#pragma unroll
    for (int off = 16; off; off >>= 1) s += __shfl_xor_sync(0xffffffffu, s, off);
    float rinv = 1.0f / fmaxf(sqrtf(s), 1e-12f);
    __half2* dh2 = (__half2*)(dh + 4 * lane);
    dh2[0] = __floats2half2_rn(v.x * rinv, v.y * rinv);
    dh2[1] = __floats2half2_rn(v.z * rinv, v.w * rinv);
}

// ---------------- kernel 1: HMMA GEMM (pure fp16) -> g_sims (fp16) ----------------
// grid (32 queryTiles, 2 candHalves, NJ) = 256 CTAs, block 512, 2 CTAs/SM.
// 16 warps in a 4x4 grid of 32q x 32c tiles; each CTA: 128q x 2048c (16 iters).
__global__ void __launch_bounds__(512, 2) gemm_kernel() {
    extern __shared__ char smem[];
    const int t = threadIdx.x, wid = t >> 5, lane = t & 31;
    const int n0 = blockIdx.x * 128;
    const int c0 = blockIdx.y * 2048;
    const int j  = blockIdx.z;
    const uint32_t sb = smem_u32(smem);

    const __half* nh = g_nhi + ((size_t)j * N_ROWS + c0) * DIMS;
    __half* simsj = g_sims + (size_t)j * N_ROWS * N_ROWS;

    // prologue: A (queries, staged once) + B tile 0
    stage_async(sb + SM_AHI, g_fhi + (size_t)n0 * DIMS, t);
    stage_async(sb + SM_B0, nh, t);
    asm volatile("cp.async.commit_group;");

    const int qoff = (wid >> 2) * 32;
    const int coff = (wid & 3) * 32;
    const int a_r  = ((lane >> 3) & 1) * 8 + (lane & 7);
    const int a_c8 = (lane >> 4) * 8;

#pragma unroll 1
    for (int it = 0; it < 16; ++it) {
        const int cur = it & 1;
        if (it < 15) {
            stage_async(sb + (cur ? SM_B0 : SM_B1), nh + (size_t)(it + 1) * 128 * DIMS, t);
            asm volatile("cp.async.commit_group;");
            asm volatile("cp.async.wait_group 1;");
        } else {
            asm volatile("cp.async.wait_group 0;");
        }
        __syncthreads();

        const uint32_t b_base = sb + (cur ? SM_B1 : SM_B0);

        float c[2][4][4];
#pragma unroll
        for (int mi = 0; mi < 2; mi++)
#pragma unroll
            for (int ni = 0; ni < 4; ni++)
#pragma unroll
                for (int e = 0; e < 4; e++) c[mi][ni][e] = 0.f;

#pragma unroll
        for (int kc = 0; kc < 8; ++kc) {
            uint32_t ah[2][4], bh[2][4];
#pragma unroll
            for (int mi = 0; mi < 2; mi++) {
                uint32_t off = toff(qoff + mi * 16 + a_r, kc * 16 + a_c8);
                ldsm4(ah[mi], sb + SM_AHI + off);
            }
#pragma unroll
            for (int g = 0; g < 2; g++) {
                uint32_t off = toff(coff + g * 16 + a_r, kc * 16 + a_c8);
                ldsm4(bh[g], b_base + off);
            }
            // frag for ni: group g=ni>>1, sel=ni&1 -> {b[g][sl], b[g][2+sl]}
#pragma unroll
            for (int mi = 0; mi < 2; mi++)
#pragma unroll
                for (int ni = 0; ni < 4; ni++) {
                    const int g = ni >> 1, sl = ni & 1;
                    mma16816(c[mi][ni], ah[mi], bh[g][sl], bh[g][2 + sl]);
                }
        }
        __syncthreads();   // smem reads done before next iter's cp.async overwrite

        // epilogue: C frag -> sims[q][cand] as fp16 (coalesced STG.32 half2)
        const int cand0 = c0 + it * 128 + coff;
#pragma unroll
        for (int mi = 0; mi < 2; mi++) {
            const int q = n0 + qoff + mi * 16 + (lane >> 2);
#pragma unroll
            for (int ni = 0; ni < 4; ni++) {
                const int cd = cand0 + ni * 8 + (lane & 3) * 2;
                *(__half2*)&simsj[(size_t)q * N_ROWS + cd] =
                    __floats2half2_rn(c[mi][ni][0], c[mi][ni][1]);
                *(__half2*)&simsj[(size_t)(q + 8) * N_ROWS + cd] =
                    __floats2half2_rn(c[mi][ni][2], c[mi][ni][3]);
            }
        }
    }
}

// ---------------- warp top-16 selection over a smem buffer ----------------
__device__ __forceinline__ float warp_select16(float* bw, int cnt, int lane,
                                               float* outp) {
    float x0 = (lane < cnt)      ? bw[lane]      : -INFINITY;
    float x1 = (lane + 32 < cnt) ? bw[lane + 32] : -INFINITY;
    float x2 = (lane + 64 < cnt) ? bw[lane + 64] : -INFINITY;
    float x3 = (lane + 96 < cnt) ? bw[lane + 96] : -INFINITY;
    float wm = -INFINITY;
#pragma unroll 1
    for (int k = 0; k < TOPK; k++) {
        float lm = fmaxf(fmaxf(x0, x1), fmaxf(x2, x3));
        wm = lm;
#pragma unroll
        for (int off = 16; off; off >>= 1)
            wm = fmaxf(wm, __shfl_xor_sync(0xffffffffu, wm, off));
        unsigned b = __ballot_sync(0xffffffffu, lm == wm);
        int leader = __ffs(b) - 1;
        if (lane == leader) {
            if      (x0 == wm) x0 = -INFINITY;
            else if (x1 == wm) x1 = -INFINITY;
            else if (x2 == wm) x2 = -INFINITY;
            else               x3 = -INFINITY;
        }
        if (lane == 0) {
            bw[k] = wm;
            if (outp) outp[k] = wm;
        }
    }
    return wm;
}

// ---------------- kernel 2: per-(row,j) top-16 over 4096 fp16 candidates ----------------
// 8 candidates per lane per iter (256/chunk) + reduce_max chunk skip.
__global__ void __launch_bounds__(256)
topk_kernel(const int* __restrict__ target, const int* __restrict__ idxp) {
    __shared__ float buf[8][128];
    const int w    = threadIdx.x >> 5;
    const int lane = threadIdx.x & 31;
    const int row  = blockIdx.x * 8 + w;
    const int j    = blockIdx.y;
    const bool maskj = (j == *idxp);
    const int  myt   = target[row];
    const __half* rowp = g_sims + ((size_t)j * N_ROWS + row) * N_ROWS;
    float* bw = buf[w];
    const unsigned lmask = (1u << lane) - 1u;

    float tau = -INFINITY;
    int   cnt = 0;

#pragma unroll 1
    for (int it = 0; it < N_ROWS / 256; ++it) {
        int c0 = it * 256 + lane * 8;
        float4 raw = *(const float4*)(rowp + c0);   // 8 halves
        const __half2* hp = (const __half2*)&raw;
        float vv[8];
#pragma unroll
        for (int p = 0; p < 4; p++) {
            float2 f = __half22float2(hp[p]);
            vv[2 * p] = f.x; vv[2 * p + 1] = f.y;
        }
        if (maskj) {
            int4 tg0 = *(const int4*)(target + c0);
            int4 tg1 = *(const int4*)(target + c0 + 4);
            const int* tg = (const int*)&tg0;
            const int* th = (const int*)&tg1;
#pragma unroll
            for (int e = 0; e < 4; e++) {
                if (tg[e] == myt) vv[e] = -1e9f;
                if (th[e] == myt) vv[4 + e] = -1e9f;
            }
        }
        // chunk screen: skip all ballots if nothing beats tau
        float lmax = vv[0];
#pragma unroll
        for (int e = 1; e < 8; e++) lmax = fmaxf(lmax, vv[e]);
        float cmax = lmax;
#pragma unroll
        for (int off = 16; off; off >>= 1)
            cmax = fmaxf(cmax, __shfl_xor_sync(0xffffffffu, cmax, off));
        if (cmax <= tau) continue;

#pragma unroll
        for (int e = 0; e < 8; e++) {
            bool p = vv[e] > tau;
            unsigned m = __ballot_sync(0xffffffffu, p);
            if (m) {
                if (p) bw[cnt + __popc(m & lmask)] = vv[e];
                cnt += __popc(m);
                __syncwarp();
                if (cnt > 96) {
                    tau = warp_select16(bw, cnt, lane, nullptr);
                    cnt = TOPK;
                    __syncwarp();
                }
            }
        }
    }
    float* outp = g_topbuf + ((size_t)row * NJ + j) * TOPK;
    warp_select16(bw, cnt, lane, outp);
}

// ---------------- kernel 3: entropy + decay, fine-grained (one (n,k) per thread) ----------------
__global__ void entropy_kernel() {
    __shared__ float red[256];
    const int id = blockIdx.x * 256 + threadIdx.x;   // 0..65535
    const int n = id >> 4, k = id & 15;
    const float* tb = g_topbuf + (size_t)n * (NJ * TOPK);

    float wsum = 0.f, w = 1.f;
#pragma unroll
    for (int i = 0; i < TOPK; i++) { wsum += w; w *= 0.95f; }
    float wk = 1.f;
    for (int i = 0; i < 16; i++) wk = (i < k) ? wk * 0.95f : wk;

    float l0 = tb[0 * TOPK + k] * 100.0f;
    float l1 = tb[1 * TOPK + k] * 100.0f;
    float l2 = tb[2 * TOPK + k] * 100.0f;
    float l3 = tb[3 * TOPK + k] * 100.0f;
    float m = fmaxf(fmaxf(l0, l1), fmaxf(l2, l3));
    float e0 = expf(l0 - m), e1 = expf(l1 - m), e2 = expf(l2 - m), e3 = expf(l3 - m);
    float s  = e0 + e1 + e2 + e3;
    float t1 = e0 * (l0 - m) + e1 * (l1 - m) + e2 * (l2 - m) + e3 * (l3 - m);
    float ent = t1 / s - logf(s);
    float acc = ent * wk / wsum;

    red[threadIdx.x] = acc;
    __syncthreads();
    for (int off = 128; off; off >>= 1) {
        if (threadIdx.x < off) red[threadIdx.x] += red[threadIdx.x + off];
        __syncthreads();
    }
    if (threadIdx.x == 0) g_part[blockIdx.x] = red[0];
}

// ---------------- kernel 4: deterministic final reduction (256 partials) ----------------
__global__ void final_kernel(float* out) {
    __shared__ float red[256];
    red[threadIdx.x] = g_part[threadIdx.x];
    __syncthreads();
    for (int off = 128; off; off >>= 1) {
        if (threadIdx.x < off) red[threadIdx.x] += red[threadIdx.x + off];
        __syncthreads();
    }
    if (threadIdx.x == 0) out[0] = red[0] / (float)N_ROWS + logf((float)NJ);
}

// ---------------- launch ----------------
extern "C" void kernel_launch(void* const* d_in, const int* in_sizes, int n_in,
                              void* d_out, int out_size) {
    const float* feat   = (const float*)d_in[0];
    const int*   target = (const int*)d_in[1];
    const float* negs   = (const float*)d_in[2];
    const int*   idxp   = (const int*)d_in[3];
    float*       out    = (float*)d_out;

    cudaFuncSetAttribute(gemm_kernel,
                         cudaFuncAttributeMaxDynamicSharedMemorySize, SM_TOTAL);

    convert_kernel<<<(N_ROWS + NJ * N_ROWS) / 8, 256>>>(feat, negs);
    gemm_kernel<<<dim3(32, 2, NJ), 512, SM_TOTAL>>>();
    topk_kernel<<<dim3(N_ROWS / 8, NJ), 256>>>(target, idxp);
    entropy_kernel<<<256, 256>>>();
    final_kernel<<<1, 256>>>(out);
}

// round 16
// speedup vs baseline: 1.0439x; 1.0439x over previous
#include <cuda_runtime.h>
#include <cuda_fp16.h>
#include <cstdint>
#include <math.h>

#define N_ROWS 4096
#define DIMS   128
#define NJ     4
#define TOPK   16

// smem map (bytes): A (32KB) + double-buffered B (2 x 32KB) = 96KB
#define SM_AHI  0
#define SM_B0   32768
#define SM_B1   65536
#define SM_TOTAL 98304

// ---------------- device scratch (static, allocation-free) ----------------
__device__ __half g_fhi[N_ROWS * DIMS];
__device__ __half g_nhi[(size_t)NJ * N_ROWS * DIMS];
__device__ __half g_sims[(size_t)NJ * N_ROWS * N_ROWS];   // 128 MB fp16
__device__ float g_topbuf[N_ROWS * NJ * TOPK];
__device__ float g_part[256];

// ---------------- PTX helpers (base-arch portable: no tcgen05) ----------------
__device__ __forceinline__ uint32_t smem_u32(const void* p) {
    uint32_t a;
    asm("{ .reg .u64 t; cvta.to.shared.u64 t, %1; cvt.u32.u64 %0, t; }" : "=r"(a) : "l"(p));
    return a;
}
__device__ __forceinline__ void ldsm4(uint32_t* r, uint32_t a) {
    asm volatile("ldmatrix.sync.aligned.m8n8.x4.shared.b16 {%0,%1,%2,%3}, [%4];"
                 : "=r"(r[0]), "=r"(r[1]), "=r"(r[2]), "=r"(r[3]) : "r"(a));
}
__device__ __forceinline__ void mma16816(float* c, const uint32_t* a,
                                         uint32_t b0, uint32_t b1) {
    asm("mma.sync.aligned.m16n8k16.row.col.f32.f16.f16.f32 "
        "{%0,%1,%2,%3}, {%4,%5,%6,%7}, {%8,%9}, {%0,%1,%2,%3};"
        : "+f"(c[0]), "+f"(c[1]), "+f"(c[2]), "+f"(c[3])
        : "r"(a[0]), "r"(a[1]), "r"(a[2]), "r"(a[3]), "r"(b0), "r"(b1));
}

// Byte offset of (row, col) in a 128x128 fp16 tile stored as 8-row x 128B
// blocked atoms with SW128 XOR swizzle. col must be a multiple of 8.
__device__ __forceinline__ uint32_t toff(int row, int col) {
    return (uint32_t)(((row >> 3) + (col >> 6) * 16) * 1024 + (row & 7) * 128 +
                      ((((col >> 3) & 7) ^ (row & 7)) * 16));
}

// Stage a 128x128 fp16 tile (row-major in gmem) into swizzled smem via cp.async.
// 512-thread version: 2048 16B chunks, 4 per thread.
__device__ __forceinline__ void stage_async(uint32_t sdst,
                                            const __half* __restrict__ g,
                                            int t) {
#pragma unroll
    for (int i = 0; i < 4; i++) {
        int c = t + 512 * i;              // 0..2047 16B chunks
        int row = c >> 4, kch = c & 15;
        uint32_t dst = sdst + toff(row, kch * 8);
        const void* src = g + row * DIMS + kch * 8;
        asm volatile("cp.async.cg.shared.global [%0], [%1], 16;" :: "r"(dst), "l"(src));
    }
}

// ---------------- kernel 0: normalize + fp16 convert ----------------
__global__ void convert_kernel(const float* __restrict__ feat,
                               const float* __restrict__ negs) {
    int gw = (blockIdx.x * blockDim.x + threadIdx.x) >> 5;
    int lane = threadIdx.x & 31;
    if (gw >= N_ROWS + NJ * N_ROWS) return;
    const float* src;
    __half* dh;
    if (gw < N_ROWS) {
        src = feat + (size_t)gw * DIMS;
        dh = g_fhi + (size_t)gw * DIMS;
    } else {
        int r = gw - N_ROWS;
        src = negs + (size_t)r * DIMS;
        dh = g_nhi + (size_t)r * DIMS;
    }
    float4 v = ((const float4*)src)[lane];
    float s = v.x * v.x + v.y * v.y + v.z * v.z + v.w * v.w;
#pragma unroll
    for (int off = 16; off; off >>= 1) s += __shfl_xor_sync(0xffffffffu, s, off);
    float rinv = 1.0f / fmaxf(sqrtf(s), 1e-12f);
    __half2* dh2 = (__half2*)(dh + 4 * lane);
    dh2[0] = __floats2half2_rn(v.x * rinv, v.y * rinv);
    dh2[1] = __floats2half2_rn(v.z * rinv, v.w * rinv);
}

// ---------------- kernel 1: HMMA GEMM (pure fp16) -> g_sims (fp16) ----------------
// grid (32 queryTiles, NJ), block 512 (16 warps; 4x4 grid of 32q x 32c tiles)
// Each CTA: 128 queries x all 4096 candidates (32 iterations), A staged once.
__global__ void __launch_bounds__(512, 1) gemm_kernel() {
    extern __shared__ char smem[];
    const int t = threadIdx.x, wid = t >> 5, lane = t & 31;
    const int n0 = blockIdx.x * 128;
    const int j  = blockIdx.y;
    const uint32_t sb = smem_u32(smem);

    const __half* nh = g_nhi + (size_t)j * N_ROWS * DIMS;
    __half* simsj = g_sims + (size_t)j * N_ROWS * N_ROWS;

    // prologue: A (queries, staged once) + B tile 0
    stage_async(sb + SM_AHI, g_fhi + (size_t)n0 * DIMS, t);
    stage_async(sb + SM_B0, nh, t);
    asm volatile("cp.async.commit_group;");

    const int qoff = (wid >> 2) * 32;
    const int coff = (wid & 3) * 32;
    const int a_r  = ((lane >> 3) & 1) * 8 + (lane & 7);
    const int a_c8 = (lane >> 4) * 8;

#pragma unroll 1
    for (int it = 0; it < 32; ++it) {
        const int cur = it & 1;
        if (it < 31) {
            stage_async(sb + (cur ? SM_B0 : SM_B1), nh + (size_t)(it + 1) * 128 * DIMS, t);
            asm volatile("cp.async.commit_group;");
            asm volatile("cp.async.wait_group 1;");
        } else {
            asm volatile("cp.async.wait_group 0;");
        }
        __syncthreads();

        const uint32_t b_base = sb + (cur ? SM_B1 : SM_B0);

        float c[2][4][4];
#pragma unroll
        for (int mi = 0; mi < 2; mi++)
#pragma unroll
            for (int ni = 0; ni < 4; ni++)
#pragma unroll
                for (int e = 0; e < 4; e++) c[mi][ni][e] = 0.f;

#pragma unroll
        for (int kc = 0; kc < 8; ++kc) {
            uint32_t ah[2][4], bh[2][4];
#pragma unroll
            for (int mi = 0; mi < 2; mi++) {
                uint32_t off = toff(qoff + mi * 16 + a_r, kc * 16 + a_c8);
                ldsm4(ah[mi], sb + SM_AHI + off);
            }
#pragma unroll
            for (int g = 0; g < 2; g++) {
                uint32_t off = toff(coff + g * 16 + a_r, kc * 16 + a_c8);
                ldsm4(bh[g], b_base + off);
            }
            // frag for ni: group g=ni>>1, sel=ni&1 -> {b[g][sl], b[g][2+sl]}
#pragma unroll
            for (int mi = 0; mi < 2; mi++)
#pragma unroll
                for (int ni = 0; ni < 4; ni++) {
                    const int g = ni >> 1, sl = ni & 1;
                    mma16816(c[mi][ni], ah[mi], bh[g][sl], bh[g][2 + sl]);
                }
        }
        __syncthreads();   // smem reads done before next iter's cp.async overwrite

        // epilogue: C frag -> sims[q][cand] as fp16 (coalesced STG.32 half2)
        const int cand0 = it * 128 + coff;
#pragma unroll
        for (int mi = 0; mi < 2; mi++) {
            const int q = n0 + qoff + mi * 16 + (lane >> 2);
#pragma unroll
            for (int ni = 0; ni < 4; ni++) {
                const int cd = cand0 + ni * 8 + (lane & 3) * 2;
                *(__half2*)&simsj[(size_t)q * N_ROWS + cd] =
                    __floats2half2_rn(c[mi][ni][0], c[mi][ni][1]);
                *(__half2*)&simsj[(size_t)(q + 8) * N_ROWS + cd] =
                    __floats2half2_rn(c[mi][ni][2], c[mi][ni][3]);
            }
        }
    }
}

// ---------------- warp top-16 selection over a smem buffer ----------------
__device__ __forceinline__ float warp_select16(float* bw, int cnt, int lane,
                                               float* outp) {
    float x0 = (lane < cnt)      ? bw[lane]      : -INFINITY;
    float x1 = (lane + 32 < cnt) ? bw[lane + 32] : -INFINITY;
    float x2 = (lane + 64 < cnt) ? bw[lane + 64] : -INFINITY;
    float x3 = (lane + 96 < cnt) ? bw[lane + 96] : -INFINITY;
    float wm = -INFINITY;
#pragma unroll 1
    for (int k = 0; k < TOPK; k++) {
        float lm = fmaxf(fmaxf(x0, x1), fmaxf(x2, x3));
        wm = lm;
#pragma unroll
        for (int off = 16; off; off >>= 1)
            wm = fmaxf(wm, __shfl_xor_sync(0xffffffffu, wm, off));
        unsigned b = __ballot_sync(0xffffffffu, lm == wm);
        int leader = __ffs(b) - 1;
        if (lane == leader) {
            if      (x0 == wm) x0 = -INFINITY;
            else if (x1 == wm) x1 = -INFINITY;
            else if (x2 == wm) x2 = -INFINITY;
            else               x3 = -INFINITY;
        }
        if (lane == 0) {
            bw[k] = wm;
            if (outp) outp[k] = wm;
        }
    }
    return wm;
}

// ---------------- kernel 2: per-(row,j) top-16 over 4096 fp16 candidates ----------------
// 8 candidates per lane per iter (256/chunk) + reduce_max chunk skip.
__global__ void __launch_bounds__(256)
topk_kernel(const int* __restrict__ target, const int* __restrict__ idxp) {
    __shared__ float buf[8][128];
    const int w    = threadIdx.x >> 5;
    const int lane = threadIdx.x & 31;
    const int row  = blockIdx.x * 8 + w;
    const int j    = blockIdx.y;
    const bool maskj = (j == *idxp);
    const int  myt   = target[row];
    const __half* rowp = g_sims + ((size_t)j * N_ROWS + row) * N_ROWS;
    float* bw = buf[w];
    const unsigned lmask = (1u << lane) - 1u;

    float tau = -INFINITY;
    int   cnt = 0;

#pragma unroll 1
    for (int it = 0; it < N_ROWS / 256; ++it) {
        int c0 = it * 256 + lane * 8;
        float4 raw = *(const float4*)(rowp + c0);   // 8 halves
        const __half2* hp = (const __half2*)&raw;
        float vv[8];
#pragma unroll
        for (int p = 0; p < 4; p++) {
            float2 f = __half22float2(hp[p]);
            vv[2 * p] = f.x; vv[2 * p + 1] = f.y;
        }
        if (maskj) {
            int4 tg0 = *(const int4*)(target + c0);
            int4 tg1 = *(const int4*)(target + c0 + 4);
            const int* tg = (const int*)&tg0;
            const int* th = (const int*)&tg1;
#pragma unroll
            for (int e = 0; e < 4; e++) {
                if (tg[e] == myt) vv[e] = -1e9f;
                if (th[e] == myt) vv[4 + e] = -1e9f;
            }
        }
        // chunk screen: skip all ballots if nothing in this 256-chunk beats tau
        float lmax = vv[0];
#pragma unroll
        for (int e = 1; e < 8; e++) lmax = fmaxf(lmax, vv[e]);
        float cmax = lmax;
#pragma unroll
        for (int off = 16; off; off >>= 1)
            cmax = fmaxf(cmax, __shfl_xor_sync(0xffffffffu, cmax, off));
        if (cmax <= tau) continue;

#pragma unroll
        for (int e = 0; e < 8; e++) {
            bool p = vv[e] > tau;
            unsigned m = __ballot_sync(0xffffffffu, p);
            if (m) {
                if (p) bw[cnt + __popc(m & lmask)] = vv[e];
                cnt += __popc(m);
                __syncwarp();
                if (cnt > 96) {
                    tau = warp_select16(bw, cnt, lane, nullptr);
                    cnt = TOPK;
                    __syncwarp();
                }
            }
        }
    }
    float* outp = g_topbuf + ((size_t)row * NJ + j) * TOPK;
    warp_select16(bw, cnt, lane, outp);
}

// ---------------- kernel 3: entropy + decay, fine-grained (one (n,k) per thread) ----------------
__global__ void entropy_kernel() {
    __shared__ float red[256];
    const int id = blockIdx.x * 256 + threadIdx.x;   // 0..65535
    const int n = id >> 4, k = id & 15;
    const float* tb = g_topbuf + (size_t)n * (NJ * TOPK);

    float wsum = 0.f, w = 1.f;
#pragma unroll
    for (int i = 0; i < TOPK; i++) { wsum += w; w *= 0.95f; }
    float wk = 1.f;
    for (int i = 0; i < 16; i++) wk = (i < k) ? wk * 0.95f : wk;

    float l0 = tb[0 * TOPK + k] * 100.0f;
    float l1 = tb[1 * TOPK + k] * 100.0f;
    float l2 = tb[2 * TOPK + k] * 100.0f;
    float l3 = tb[3 * TOPK + k] * 100.0f;
    float m = fmaxf(fmaxf(l0, l1), fmaxf(l2, l3));
    float e0 = expf(l0 - m), e1 = expf(l1 - m), e2 = expf(l2 - m), e3 = expf(l3 - m);
    float s  = e0 + e1 + e2 + e3;
    float t1 = e0 * (l0 - m) + e1 * (l1 - m) + e2 * (l2 - m) + e3 * (l3 - m);
    float ent = t1 / s - logf(s);
    float acc = ent * wk / wsum;

    red[threadIdx.x] = acc;
    __syncthreads();
    for (int off = 128; off; off >>= 1) {
        if (threadIdx.x < off) red[threadIdx.x] += red[threadIdx.x + off];
        __syncthreads();
    }
    if (threadIdx.x == 0) g_part[blockIdx.x] = red[0];
}

// ---------------- kernel 4: deterministic final reduction (256 partials) ----------------
__global__ void final_kernel(float* out) {
    __shared__ float red[256];
    red[threadIdx.x] = g_part[threadIdx.x];
    __syncthreads();
    for (int off = 128; off; off >>= 1) {
        if (threadIdx.x < off) red[threadIdx.x] += red[threadIdx.x + off];
        __syncthreads();
    }
    if (threadIdx.x == 0) out[0] = red[0] / (float)N_ROWS + logf((float)NJ);
}

// ---------------- launch ----------------
extern "C" void kernel_launch(void* const* d_in, const int* in_sizes, int n_in,
                              void* d_out, int out_size) {
    const float* feat   = (const float*)d_in[0];
    const int*   target = (const int*)d_in[1];
    const float* negs   = (const float*)d_in[2];
    const int*   idxp   = (const int*)d_in[3];
    float*       out    = (float*)d_out;

    cudaFuncSetAttribute(gemm_kernel,
                         cudaFuncAttributeMaxDynamicSharedMemorySize, SM_TOTAL);

    convert_kernel<<<(N_ROWS + NJ * N_ROWS) / 8, 256>>>(feat, negs);
    gemm_kernel<<<dim3(32, NJ), 512, SM_TOTAL>>>();
    topk_kernel<<<dim3(N_ROWS / 8, NJ), 256>>>(target, idxp);
    entropy_kernel<<<256, 256>>>();
    final_kernel<<<1, 256>>>(out);
}